// round 13
// baseline (speedup 1.0000x reference)
#include <cuda_runtime.h>
#include <cstdint>

// Problem constants
#define NN   30000
#define EE   480000
#define GG   64
#define INC  24
#define HH   512
#define LL   6

// ---------------------------------------------------------------------------
// Scratch (device globals). "I" suffix = interleaved (hi,lo) pairs: buf[2*i]=hi, buf[2*i+1]=lo
// ---------------------------------------------------------------------------
__device__ __align__(16) float g_h  [(size_t)NN * HH];            // node state (raw)
__device__ __align__(16) float g_hI [(size_t)NN * HH * 2];        // h interleaved
__device__ __align__(16) float g_t1I[(size_t)NN * HH * 2];        // MLP hidden interleaved
__device__ __align__(16) float g_msg[(size_t)NN * HH];            // per-node message
__device__ __align__(16) float g_m  [(size_t)NN * HH];            // aggregated message
__device__ __align__(16) float g_mI [(size_t)NN * HH * 2];        // m interleaved
__device__ __align__(16) float g_gi [(size_t)NN * 3 * HH];        // GRU input gates
__device__ __align__(16) float g_gh [(size_t)NN * 3 * HH];        // GRU hidden gates
// interleaved weight splits (once per launch)
__device__ __align__(16) float g_w1I [(size_t)LL * HH * HH * 2];
__device__ __align__(16) float g_w2I [(size_t)LL * HH * HH * 2];
__device__ __align__(16) float g_wihI[(size_t)LL * HH * 3 * HH * 2];
__device__ __align__(16) float g_whhI[(size_t)LL * HH * 3 * HH * 2];

__device__ float g_pool[GG * HH];
__device__ float g_cnt [GG];
__device__ int   g_eidx[2 * EE];
__device__ int   g_batch[NN];
__device__ int   g_flag[2];

// ---------------------------------------------------------------------------
// tf32 helpers
// ---------------------------------------------------------------------------
__device__ __forceinline__ uint32_t f2tf32(float f)
{
    uint32_t u;
    asm("cvt.rna.tf32.f32 %0, %1;" : "=r"(u) : "f"(f));
    return u;
}
__device__ __forceinline__ void split_tf32(float v, float& hi, float& lo)
{
    hi = __uint_as_float(f2tf32(v));
    lo = __uint_as_float(f2tf32(v - hi));
}

// ---------------------------------------------------------------------------
// dtype detection + conversion
// ---------------------------------------------------------------------------
__global__ void detect_both_k(const unsigned* __restrict__ pe,
                              const unsigned* __restrict__ pb)
{
    __shared__ int any;
    if (threadIdx.x == 0) any = 0;
    __syncthreads();
    const unsigned* p = (blockIdx.x == 0) ? pe : pb;
    int pairs = (blockIdx.x == 0) ? EE : (NN / 2);
    int lim = pairs < 8192 ? pairs : 8192;
    for (int i = threadIdx.x; i < lim; i += blockDim.x)
        if (p[2 * i + 1] != 0u) any = 1;
    __syncthreads();
    if (threadIdx.x == 0) g_flag[blockIdx.x] = (any == 0) ? 1 : 0;
}

__global__ void convert_both_k(const void* __restrict__ e, const void* __restrict__ b)
{
    int i = blockIdx.x * blockDim.x + threadIdx.x;
    if (i < 2 * EE) {
        g_eidx[i] = g_flag[0] ? (int)(((const long long*)e)[i])
                              : ((const int*)e)[i];
    } else if (i < 2 * EE + NN) {
        int j = i - 2 * EE;
        g_batch[j] = g_flag[1] ? (int)(((const long long*)b)[j])
                               : ((const int*)b)[j];
    }
}

// ---------------------------------------------------------------------------
// Split pass: fp32 buffer -> interleaved (hi,lo) buffer (out[2i]=hi_i, out[2i+1]=lo_i)
// ---------------------------------------------------------------------------
__global__ void split_int_k(const float4* __restrict__ in, float4* __restrict__ outI, int n4)
{
    int i = blockIdx.x * blockDim.x + threadIdx.x;
    if (i >= n4) return;
    float4 v = in[i];
    float hx, lx, hy, ly, hz, lz, hw, lw;
    split_tf32(v.x, hx, lx);
    split_tf32(v.y, hy, ly);
    split_tf32(v.z, hz, lz);
    split_tf32(v.w, hw, lw);
    outI[2 * i]     = make_float4(hx, lx, hy, ly);
    outI[2 * i + 1] = make_float4(hz, lz, hw, lw);
}

// ---------------------------------------------------------------------------
// Interleaved 3xTF32 GEMM.
// AI: [M][2K] interleaved rows; WI: [K][2Nc] interleaved rows.
// acc += Ah*Wh + Al*Wh + Ah*Wl (fp32 accum). Inner loop: LDS.64 + MMA only.
// BM=128, BN=128, BK=16, 3 stages, 256 thr, warp tile 64x32 (2m x 4n),
// mma.m16n8k8.tf32, 2 CTAs/SM.
// blockIdx.z selects problem {A,W,bias,C} vs {A2,W2,bias2,Cz2} (merged GRU GEMMs).
// Outputs: raw C, dup C2, interleaved-split CI (any may be null).
// ---------------------------------------------------------------------------
#define BM 128
#define BN 128
#define BK 16
#define STAGES 3
#define AS3 40                       // 32 data + 8 pad floats per A row
#define BS3 264                      // 256 data + 8 pad floats per B row
#define A_FL (BM * AS3)              // 5120 floats
#define B_FL (BK * BS3)              // 4224 floats
#define STG_FL (A_FL + B_FL)         // 9344 floats
#define GEMM_SMEM_BYTES (STAGES * STG_FL * 4)   // 112,128 B

__device__ __forceinline__ void cp_async16(float* s, const float* g, bool pred)
{
    unsigned saddr = (unsigned)__cvta_generic_to_shared(s);
    int sz = pred ? 16 : 0;
    asm volatile("cp.async.cg.shared.global [%0], [%1], 16, %2;\n"
                 :: "r"(saddr), "l"(g), "r"(sz));
}

__device__ __forceinline__ void mma_tf32(float* d, const uint32_t* a, const uint32_t* b)
{
    asm volatile(
        "mma.sync.aligned.m16n8k8.row.col.f32.tf32.tf32.f32 "
        "{%0,%1,%2,%3}, {%4,%5,%6,%7}, {%8,%9}, {%0,%1,%2,%3};"
        : "+f"(d[0]), "+f"(d[1]), "+f"(d[2]), "+f"(d[3])
        : "r"(a[0]), "r"(a[1]), "r"(a[2]), "r"(a[3]), "r"(b[0]), "r"(b[1]));
}

__device__ __forceinline__ void load_stage_i(float* sbase,
                                             const float* __restrict__ AI,
                                             const float* __restrict__ WI,
                                             int M, int K, int Nc,
                                             int bm, int bn, int k0, int tid)
{
    float* sA = sbase;
    float* sB = sbase + A_FL;
    // A: 128 rows x 8 float4 (32 floats of interleaved data); 2 threads/row, 4 f4 each
    int arow = tid >> 1;
    int af   = tid & 1;
    const float* ag = AI + (size_t)(bm + arow) * (2 * K) + 2 * k0;
    float* as = sA + arow * AS3;
    bool av = (bm + arow) < M;
#pragma unroll
    for (int i = 0; i < 4; i++) {
        int f4 = af + 2 * i;            // 0..7
        cp_async16(as + 4 * f4, ag + 4 * f4, av);
    }
    // B: 16 rows x 64 float4 (256 floats interleaved); 16 threads/row, 4 f4 each
    int brow = tid >> 4;                // 0..15
    int bc   = tid & 15;                // 0..15
    const float* bg = WI + (size_t)(k0 + brow) * (2 * Nc) + 2 * bn;
    float* bs = sB + brow * BS3;
#pragma unroll
    for (int j = 0; j < 4; j++) {
        int f4 = bc + 16 * j;           // 0..63
        cp_async16(bs + 4 * f4, bg + 4 * f4, true);
    }
}

__global__ __launch_bounds__(256, 2)
void tf32gemm_i(const float* __restrict__ AI,  const float* __restrict__ WI,
                const float* __restrict__ bias, float* __restrict__ C,
                const float* __restrict__ AI2, const float* __restrict__ WI2,
                const float* __restrict__ bias2, float* __restrict__ Cz2,
                float* __restrict__ C2, float* __restrict__ CI,
                int M, int K, int Nc, int do_relu)
{
    if (blockIdx.z == 1) { AI = AI2; WI = WI2; bias = bias2; C = Cz2; }

    extern __shared__ float smem[];
    const int tid  = threadIdx.x;
    const int bm   = blockIdx.y * BM;
    const int bn   = blockIdx.x * BN;
    const int warp = tid >> 5, lane = tid & 31;
    const int wm   = (warp >> 2) * 64;   // 0 or 64
    const int wn   = (warp & 3) * 32;    // 0,32,64,96
    const int gid  = lane >> 2, tig = lane & 3;

    float acc[4][4][4];
#pragma unroll
    for (int mt = 0; mt < 4; mt++)
#pragma unroll
        for (int nt = 0; nt < 4; nt++)
#pragma unroll
            for (int r = 0; r < 4; r++) acc[mt][nt][r] = 0.f;

    const int kTiles = K / BK;

    load_stage_i(smem, AI, WI, M, K, Nc, bm, bn, 0, tid);
    asm volatile("cp.async.commit_group;\n");
    load_stage_i(smem + STG_FL, AI, WI, M, K, Nc, bm, bn, BK, tid);
    asm volatile("cp.async.commit_group;\n");
    asm volatile("cp.async.wait_group 1;\n");
    __syncthreads();

    for (int kt = 0; kt < kTiles; kt++) {
        float* sA = smem + (kt % STAGES) * STG_FL;
        float* sB = sA + A_FL;

        if (kt + 2 < kTiles)
            load_stage_i(smem + ((kt + 2) % STAGES) * STG_FL,
                         AI, WI, M, K, Nc, bm, bn, (kt + 2) * BK, tid);
        asm volatile("cp.async.commit_group;\n");

#pragma unroll
        for (int ks = 0; ks < 2; ks++) {
            const int c0 = ks * 8 + tig, c1 = c0 + 4;
            uint32_t ah[4][4], al[4][4];
#pragma unroll
            for (int mt = 0; mt < 4; mt++) {
                int r0 = wm + mt * 16 + gid;
                float2 p00 = *(const float2*)(sA + r0 * AS3 + 2 * c0);
                float2 p10 = *(const float2*)(sA + (r0 + 8) * AS3 + 2 * c0);
                float2 p01 = *(const float2*)(sA + r0 * AS3 + 2 * c1);
                float2 p11 = *(const float2*)(sA + (r0 + 8) * AS3 + 2 * c1);
                ah[mt][0] = __float_as_uint(p00.x); al[mt][0] = __float_as_uint(p00.y);
                ah[mt][1] = __float_as_uint(p10.x); al[mt][1] = __float_as_uint(p10.y);
                ah[mt][2] = __float_as_uint(p01.x); al[mt][2] = __float_as_uint(p01.y);
                ah[mt][3] = __float_as_uint(p11.x); al[mt][3] = __float_as_uint(p11.y);
            }
#pragma unroll
            for (int nt = 0; nt < 4; nt++) {
                int col = wn + nt * 8 + gid;
                float2 q0 = *(const float2*)(sB + c0 * BS3 + 2 * col);
                float2 q1 = *(const float2*)(sB + c1 * BS3 + 2 * col);
                uint32_t bh[2], bl[2];
                bh[0] = __float_as_uint(q0.x); bl[0] = __float_as_uint(q0.y);
                bh[1] = __float_as_uint(q1.x); bl[1] = __float_as_uint(q1.y);
#pragma unroll
                for (int mt = 0; mt < 4; mt++) {
                    mma_tf32(acc[mt][nt], ah[mt], bh);   // hi*hi
                    mma_tf32(acc[mt][nt], al[mt], bh);   // lo*hi
                    mma_tf32(acc[mt][nt], ah[mt], bl);   // hi*lo
                }
            }
        }

        asm volatile("cp.async.wait_group 1;\n");
        __syncthreads();
    }

    // Epilogue
#pragma unroll
    for (int nt = 0; nt < 4; nt++) {
        int col = bn + wn + nt * 8 + tig * 2;
        float b0 = bias[col], b1 = bias[col + 1];
#pragma unroll
        for (int mt = 0; mt < 4; mt++) {
            int r0 = bm + wm + mt * 16 + gid;
            int r1 = r0 + 8;
            float v0 = acc[mt][nt][0] + b0;
            float v1 = acc[mt][nt][1] + b1;
            float v2 = acc[mt][nt][2] + b0;
            float v3 = acc[mt][nt][3] + b1;
            if (do_relu) {
                v0 = fmaxf(v0, 0.f); v1 = fmaxf(v1, 0.f);
                v2 = fmaxf(v2, 0.f); v3 = fmaxf(v3, 0.f);
            }
            if (r0 < M) {
                size_t o = (size_t)r0 * Nc + col;
                if (C)  *(float2*)(C + o)  = make_float2(v0, v1);
                if (C2) *(float2*)(C2 + o) = make_float2(v0, v1);
                if (CI) {
                    float h0, l0, h1, l1;
                    split_tf32(v0, h0, l0); split_tf32(v1, h1, l1);
                    *(float4*)(CI + (size_t)r0 * 2 * Nc + 2 * col) = make_float4(h0, l0, h1, l1);
                }
            }
            if (r1 < M) {
                size_t o = (size_t)r1 * Nc + col;
                if (C)  *(float2*)(C + o)  = make_float2(v2, v3);
                if (C2) *(float2*)(C2 + o) = make_float2(v2, v3);
                if (CI) {
                    float h2, l2, h3, l3;
                    split_tf32(v2, h2, l2); split_tf32(v3, h3, l3);
                    *(float4*)(CI + (size_t)r1 * 2 * Nc + 2 * col) = make_float4(h2, l2, h3, l3);
                }
            }
        }
    }
}

// ---------------------------------------------------------------------------
// SIMT SGEMM (encoder, K=24): h = x@W + bias (raw + interleaved split out)
// ---------------------------------------------------------------------------
__global__ __launch_bounds__(256, 2)
void sgemm_enc(const float* __restrict__ A, const float* __restrict__ W,
               const float* __restrict__ bias, float* __restrict__ C,
               float* __restrict__ CI, int M, int K, int Nc)
{
    __shared__ float As[2][8][128];
    __shared__ float Bs[2][8][128];

    const int tid = threadIdx.x;
    const int bm = blockIdx.y * 128;
    const int bn = blockIdx.x * 128;

    const int arow = tid >> 1;
    const int acol = (tid & 1) << 2;
    const int brow = tid >> 5;
    const int bcol = (tid & 31) << 2;
    const int ty = tid >> 4;
    const int tx = tid & 15;

    float acc[8][8];
#pragma unroll
    for (int i = 0; i < 8; i++)
#pragma unroll
        for (int j = 0; j < 8; j++) acc[i][j] = 0.f;

    const int grow = bm + arow;
    const float* Arow = A + (size_t)grow * K;

    float4 av, bv;
    av = (grow < M) ? *(const float4*)(Arow + acol) : make_float4(0.f, 0.f, 0.f, 0.f);
    bv = *(const float4*)(W + (size_t)brow * Nc + bn + bcol);
    As[0][acol + 0][arow] = av.x; As[0][acol + 1][arow] = av.y;
    As[0][acol + 2][arow] = av.z; As[0][acol + 3][arow] = av.w;
    *(float4*)&Bs[0][brow][bcol] = bv;
    __syncthreads();

    int buf = 0;
    for (int k0 = 0; k0 < K; k0 += 8) {
        const bool next = (k0 + 8) < K;
        if (next) {
            av = (grow < M) ? *(const float4*)(Arow + k0 + 8 + acol)
                            : make_float4(0.f, 0.f, 0.f, 0.f);
            bv = *(const float4*)(W + (size_t)(k0 + 8 + brow) * Nc + bn + bcol);
        }
#pragma unroll
        for (int kk = 0; kk < 8; kk++) {
            float4 a0 = *(const float4*)&As[buf][kk][ty * 8];
            float4 a1 = *(const float4*)&As[buf][kk][ty * 8 + 4];
            float4 b0 = *(const float4*)&Bs[buf][kk][tx * 8];
            float4 b1 = *(const float4*)&Bs[buf][kk][tx * 8 + 4];
            float a[8] = {a0.x, a0.y, a0.z, a0.w, a1.x, a1.y, a1.z, a1.w};
            float b[8] = {b0.x, b0.y, b0.z, b0.w, b1.x, b1.y, b1.z, b1.w};
#pragma unroll
            for (int i = 0; i < 8; i++)
#pragma unroll
                for (int j = 0; j < 8; j++)
                    acc[i][j] = fmaf(a[i], b[j], acc[i][j]);
        }
        if (next) {
            const int nbuf = buf ^ 1;
            As[nbuf][acol + 0][arow] = av.x; As[nbuf][acol + 1][arow] = av.y;
            As[nbuf][acol + 2][arow] = av.z; As[nbuf][acol + 3][arow] = av.w;
            *(float4*)&Bs[nbuf][brow][bcol] = bv;
            __syncthreads();
            buf = nbuf;
        }
    }

    float bvals[8];
#pragma unroll
    for (int j = 0; j < 8; j++) bvals[j] = bias[bn + tx * 8 + j];
#pragma unroll
    for (int i = 0; i < 8; i++) {
        int row = bm + ty * 8 + i;
        if (row >= M) continue;
        float o[8], oh[8], ol[8];
#pragma unroll
        for (int j = 0; j < 8; j++) {
            o[j] = acc[i][j] + bvals[j];
            split_tf32(o[j], oh[j], ol[j]);
        }
        size_t off = (size_t)row * Nc + bn + tx * 8;
        float4* cp = (float4*)(C + off);
        cp[0] = make_float4(o[0], o[1], o[2], o[3]);
        cp[1] = make_float4(o[4], o[5], o[6], o[7]);
        float4* ci = (float4*)(CI + 2 * off);
        ci[0] = make_float4(oh[0], ol[0], oh[1], ol[1]);
        ci[1] = make_float4(oh[2], ol[2], oh[3], ol[3]);
        ci[2] = make_float4(oh[4], ol[4], oh[5], ol[5]);
        ci[3] = make_float4(oh[6], ol[6], oh[7], ol[7]);
    }
}

// ---------------------------------------------------------------------------
// Edge scatter: m[dst] += msg[src]  (warp/edge, vector red.global.v4.f32)
// ---------------------------------------------------------------------------
__global__ void scatter_k(const float* __restrict__ msg, float* __restrict__ m)
{
    int gw = (blockIdx.x * blockDim.x + threadIdx.x) >> 5;
    int lane = threadIdx.x & 31;
    if (gw >= EE) return;
    int s = g_eidx[gw];
    int d = g_eidx[EE + gw];
    const float4* ms = (const float4*)(msg + (size_t)s * HH);
    float4* md = (float4*)(m + (size_t)d * HH);
#pragma unroll
    for (int i = 0; i < 4; i++) {
        int c = lane + i * 32;
        float4 v = __ldg(ms + c);
        asm volatile("red.global.add.v4.f32 [%0], {%1,%2,%3,%4};"
                     :: "l"(md + c), "f"(v.x), "f"(v.y), "f"(v.z), "f"(v.w)
                     : "memory");
    }
}

// ---------------------------------------------------------------------------
// GRU gate update (in place on h) + interleaved h split
// ---------------------------------------------------------------------------
__device__ __forceinline__ float sigm_f(float x) { return 1.f / (1.f + __expf(-x)); }
__device__ __forceinline__ float tanh_f(float x) { return 1.f - 2.f / (__expf(2.f * x) + 1.f); }
__device__ __forceinline__ float gru1(float gir, float giz, float gin,
                                      float ghr, float ghz, float ghn, float h)
{
    float r = sigm_f(gir + ghr);
    float z = sigm_f(giz + ghz);
    float n = tanh_f(gin + r * ghn);
    return (1.f - z) * n + z * h;
}

__global__ void gate_k(const float* __restrict__ gi, const float* __restrict__ gh,
                       float* __restrict__ h, float* __restrict__ hI)
{
    int idx = blockIdx.x * blockDim.x + threadIdx.x;
    if (idx >= NN * (HH / 4)) return;
    int row = idx >> 7;
    int c4  = idx & 127;
    const float4* gip = (const float4*)(gi + (size_t)row * 3 * HH) + c4;
    const float4* ghp = (const float4*)(gh + (size_t)row * 3 * HH) + c4;
    float4 gir = gip[0],   giz = gip[128], gin = gip[256];
    float4 ghr = ghp[0],   ghz = ghp[128], ghn = ghp[256];
    float4 hv = ((const float4*)h)[idx];
    float4 o;
    o.x = gru1(gir.x, giz.x, gin.x, ghr.x, ghz.x, ghn.x, hv.x);
    o.y = gru1(gir.y, giz.y, gin.y, ghr.y, ghz.y, ghn.y, hv.y);
    o.z = gru1(gir.z, giz.z, gin.z, ghr.z, ghz.z, ghn.z, hv.z);
    o.w = gru1(gir.w, giz.w, gin.w, ghr.w, ghz.w, ghn.w, hv.w);
    ((float4*)h)[idx] = o;
    float hx, lx, hy, ly, hz, lz, hw, lw;
    split_tf32(o.x, hx, lx); split_tf32(o.y, hy, ly);
    split_tf32(o.z, hz, lz); split_tf32(o.w, hw, lw);
    ((float4*)hI)[2 * idx]     = make_float4(hx, lx, hy, ly);
    ((float4*)hI)[2 * idx + 1] = make_float4(hz, lz, hw, lw);
}

// ---------------------------------------------------------------------------
// Pooling + head
// ---------------------------------------------------------------------------
__global__ void zero_pool_k()
{
    int i = blockIdx.x * blockDim.x + threadIdx.x;
    if (i < GG * HH) g_pool[i] = 0.f;
    if (i < GG) g_cnt[i] = 0.f;
}

__global__ void pool_k(const float* __restrict__ h)
{
    int idx = blockIdx.x * blockDim.x + threadIdx.x;
    if (idx >= NN * 128) return;
    int row = idx >> 7;
    int c4  = idx & 127;
    int g   = g_batch[row];
    float4 v = ((const float4*)h)[idx];
    float* p = &g_pool[g * HH + c4 * 4];
    asm volatile("red.global.add.v4.f32 [%0], {%1,%2,%3,%4};"
                 :: "l"(p), "f"(v.x), "f"(v.y), "f"(v.z), "f"(v.w)
                 : "memory");
    if (c4 == 0) atomicAdd(&g_cnt[g], 1.f);
}

__global__ void head_k(const float* __restrict__ w1, const float* __restrict__ b1,
                       const float* __restrict__ w2, const float* __restrict__ b2,
                       float* __restrict__ out)
{
    __shared__ float p[HH];
    __shared__ float red[256];
    int g = blockIdx.x, t = threadIdx.x;
    float inv = 1.f / fmaxf(g_cnt[g], 1.f);
    for (int c = t; c < HH; c += 256) p[c] = g_pool[g * HH + c] * inv;
    __syncthreads();
    float acc = b1[t];
    for (int k = 0; k < HH; k++) acc = fmaf(p[k], w1[k * 256 + t], acc);
    acc = fmaxf(acc, 0.f) * w2[t];
    red[t] = acc;
    __syncthreads();
    for (int s = 128; s > 0; s >>= 1) {
        if (t < s) red[t] += red[t + s];
        __syncthreads();
    }
    if (t == 0) out[g] = red[0] + b2[0];
}

// ---------------------------------------------------------------------------
// Launch
// ---------------------------------------------------------------------------
extern "C" void kernel_launch(void* const* d_in, const int* in_sizes, int n_in,
                              void* d_out, int out_size)
{
    const float* x       = (const float*)d_in[0];
    const void*  eidx    = d_in[1];
    const void*  batch   = d_in[2];
    const float* enc_w   = (const float*)d_in[3];
    const float* enc_b   = (const float*)d_in[4];
    const float* mlp_w1  = (const float*)d_in[5];
    const float* mlp_b1  = (const float*)d_in[6];
    const float* mlp_w2  = (const float*)d_in[7];
    const float* mlp_b2  = (const float*)d_in[8];
    const float* gru_wih = (const float*)d_in[9];
    const float* gru_whh = (const float*)d_in[10];
    const float* gru_bih = (const float*)d_in[11];
    const float* gru_bhh = (const float*)d_in[12];
    const float* head_w1 = (const float*)d_in[13];
    const float* head_b1 = (const float*)d_in[14];
    const float* head_w2 = (const float*)d_in[15];
    const float* head_b2 = (const float*)d_in[16];
    float* out = (float*)d_out;

    float *ph, *phI, *pt1I, *pmsg, *pm, *pmI, *pgi, *pgh;
    float *pw1I, *pw2I, *pwihI, *pwhhI;
    cudaGetSymbolAddress((void**)&ph,    g_h);
    cudaGetSymbolAddress((void**)&phI,   g_hI);
    cudaGetSymbolAddress((void**)&pt1I,  g_t1I);
    cudaGetSymbolAddress((void**)&pmsg,  g_msg);
    cudaGetSymbolAddress((void**)&pm,    g_m);
    cudaGetSymbolAddress((void**)&pmI,   g_mI);
    cudaGetSymbolAddress((void**)&pgi,   g_gi);
    cudaGetSymbolAddress((void**)&pgh,   g_gh);
    cudaGetSymbolAddress((void**)&pw1I,  g_w1I);
    cudaGetSymbolAddress((void**)&pw2I,  g_w2I);
    cudaGetSymbolAddress((void**)&pwihI, g_wihI);
    cudaGetSymbolAddress((void**)&pwhhI, g_whhI);

    cudaFuncSetAttribute(tf32gemm_i, cudaFuncAttributeMaxDynamicSharedMemorySize,
                         GEMM_SMEM_BYTES);

    // dtype detection + index conversion
    detect_both_k<<<2, 256>>>((const unsigned*)eidx, (const unsigned*)batch);
    convert_both_k<<<(2 * EE + NN + 255) / 256, 256>>>(eidx, batch);

    // interleaved weight splits (once per launch)
    const int nW1 = LL * HH * HH / 4;
    const int nWG = LL * HH * 3 * HH / 4;
    split_int_k<<<(nW1 + 255) / 256, 256>>>((const float4*)mlp_w1,  (float4*)pw1I,  nW1);
    split_int_k<<<(nW1 + 255) / 256, 256>>>((const float4*)mlp_w2,  (float4*)pw2I,  nW1);
    split_int_k<<<(nWG + 255) / 256, 256>>>((const float4*)gru_wih, (float4*)pwihI, nWG);
    split_int_k<<<(nWG + 255) / 256, 256>>>((const float4*)gru_whh, (float4*)pwhhI, nWG);

    dim3 gEnc(HH / 128, (NN + 127) / 128);
    dim3 gMsg(HH / BN, (NN + BM - 1) / BM, 1);             // (4, 235, 1)
    dim3 gGru(3 * HH / BN, (NN + BM - 1) / BM, 2);         // (12, 235, 2)
    const int nAct4 = NN * HH / 4;

    // encoder: h = x @ enc_w + enc_b (exact fp32) + interleaved split
    sgemm_enc<<<gEnc, 256>>>(x, enc_w, enc_b, ph, phI, NN, INC, HH);

    for (int l = 0; l < LL; l++) {
        // t1 = relu(h @ w1 + b1) -> interleaved only
        tf32gemm_i<<<gMsg, 256, GEMM_SMEM_BYTES>>>(
            phI, pw1I + (size_t)l * 2 * HH * HH, mlp_b1 + (size_t)l * HH, nullptr,
            nullptr, nullptr, nullptr, nullptr,
            nullptr, pt1I, NN, HH, HH, 1);
        // msg = t1 @ w2 + b2 ; m = msg (self-loop dual store)
        tf32gemm_i<<<gMsg, 256, GEMM_SMEM_BYTES>>>(
            pt1I, pw2I + (size_t)l * 2 * HH * HH, mlp_b2 + (size_t)l * HH, pmsg,
            nullptr, nullptr, nullptr, nullptr,
            pm, nullptr, NN, HH, HH, 0);
        // m[dst] += msg[src]
        scatter_k<<<(EE + 7) / 8, 256>>>(pmsg, pm);
        // split m -> interleaved
        split_int_k<<<(nAct4 + 255) / 256, 256>>>((const float4*)pm, (float4*)pmI, nAct4);
        // merged GRU GEMMs: z=0: gi = m@wih + bih ; z=1: gh = h@whh + bhh
        tf32gemm_i<<<gGru, 256, GEMM_SMEM_BYTES>>>(
            pmI, pwihI + (size_t)l * 2 * HH * 3 * HH, gru_bih + (size_t)l * 3 * HH, pgi,
            phI, pwhhI + (size_t)l * 2 * HH * 3 * HH, gru_bhh + (size_t)l * 3 * HH, pgh,
            nullptr, nullptr, NN, HH, 3 * HH, 0);
        // h = GRU(h, m) + interleaved split
        gate_k<<<(NN * 128 + 255) / 256, 256>>>(pgi, pgh, ph, phI);
    }

    // global mean pool + head
    zero_pool_k<<<(GG * HH + 255) / 256, 256>>>();
    pool_k<<<(NN * 128 + 255) / 256, 256>>>(ph);
    head_k<<<GG, 256>>>(head_w1, head_b1, head_w2, head_b2, out);
}

// round 17
// speedup vs baseline: 1.3561x; 1.3561x over previous
#include <cuda_runtime.h>
#include <cstdint>

// Problem constants
#define NN   30000
#define EE   480000
#define GG   64
#define INC  24
#define HH   512
#define LL   6

// ---------------------------------------------------------------------------
// Scratch (device globals — no allocations allowed anywhere)
// ---------------------------------------------------------------------------
__device__ __align__(16) float g_h  [(size_t)NN * HH];        // node state (raw)
__device__ __align__(16) float g_hh [(size_t)NN * HH];        // h hi
__device__ __align__(16) float g_hl [(size_t)NN * HH];        // h lo
__device__ __align__(16) float g_t1h[(size_t)NN * HH];        // relu MLP hidden hi
__device__ __align__(16) float g_t1l[(size_t)NN * HH];        // relu MLP hidden lo
__device__ __align__(16) float g_msg[(size_t)NN * HH];        // per-node message
__device__ __align__(16) float g_m  [(size_t)NN * HH];        // aggregated message
__device__ __align__(16) float g_mh [(size_t)NN * HH];        // m hi
__device__ __align__(16) float g_ml [(size_t)NN * HH];        // m lo
__device__ __align__(16) float g_gi [(size_t)NN * 3 * HH];    // GRU input gates
__device__ __align__(16) float g_gh [(size_t)NN * 3 * HH];    // GRU hidden gates
// weight splits (computed once per launch)
__device__ __align__(16) float g_w1h[(size_t)LL * HH * HH];
__device__ __align__(16) float g_w1l[(size_t)LL * HH * HH];
__device__ __align__(16) float g_w2h[(size_t)LL * HH * HH];
__device__ __align__(16) float g_w2l[(size_t)LL * HH * HH];
__device__ __align__(16) float g_wihh[(size_t)LL * HH * 3 * HH];
__device__ __align__(16) float g_wihl[(size_t)LL * HH * 3 * HH];
__device__ __align__(16) float g_whhh[(size_t)LL * HH * 3 * HH];
__device__ __align__(16) float g_whhl[(size_t)LL * HH * 3 * HH];

__device__ float g_pool[GG * HH];
__device__ float g_cnt [GG];
__device__ int   g_eidx[2 * EE];
__device__ int   g_batch[NN];
__device__ int   g_flag[2];

// ---------------------------------------------------------------------------
// tf32 helpers
// ---------------------------------------------------------------------------
__device__ __forceinline__ uint32_t f2tf32(float f)
{
    uint32_t u;
    asm("cvt.rna.tf32.f32 %0, %1;" : "=r"(u) : "f"(f));
    return u;
}
__device__ __forceinline__ void split_tf32(float v, float& hi, float& lo)
{
    hi = __uint_as_float(f2tf32(v));
    lo = __uint_as_float(f2tf32(v - hi));
}

// ---------------------------------------------------------------------------
// dtype detection (block 0 = edges, block 1 = batch):
// int64 buffers (values < 2^31) have all odd 32-bit words == 0
// ---------------------------------------------------------------------------
__global__ void detect_both_k(const unsigned* __restrict__ pe,
                              const unsigned* __restrict__ pb)
{
    __shared__ int any;
    if (threadIdx.x == 0) any = 0;
    __syncthreads();
    const unsigned* p = (blockIdx.x == 0) ? pe : pb;
    int pairs = (blockIdx.x == 0) ? EE : (NN / 2);
    int lim = pairs < 8192 ? pairs : 8192;
    for (int i = threadIdx.x; i < lim; i += blockDim.x)
        if (p[2 * i + 1] != 0u) any = 1;
    __syncthreads();
    if (threadIdx.x == 0) g_flag[blockIdx.x] = (any == 0) ? 1 : 0;
}

__global__ void convert_both_k(const void* __restrict__ e, const void* __restrict__ b)
{
    int i = blockIdx.x * blockDim.x + threadIdx.x;
    if (i < 2 * EE) {
        g_eidx[i] = g_flag[0] ? (int)(((const long long*)e)[i])
                              : ((const int*)e)[i];
    } else if (i < 2 * EE + NN) {
        int j = i - 2 * EE;
        g_batch[j] = g_flag[1] ? (int)(((const long long*)b)[j])
                               : ((const int*)b)[j];
    }
}

// ---------------------------------------------------------------------------
// Split pass: hi/lo decomposition (separate outputs, float4 vectorized)
// ---------------------------------------------------------------------------
__global__ void split_k(const float4* __restrict__ in, float4* __restrict__ hi,
                        float4* __restrict__ lo, int n4)
{
    int i = blockIdx.x * blockDim.x + threadIdx.x;
    if (i >= n4) return;
    float4 v = in[i];
    float4 h4, l4;
    split_tf32(v.x, h4.x, l4.x);
    split_tf32(v.y, h4.y, l4.y);
    split_tf32(v.z, h4.z, l4.z);
    split_tf32(v.w, h4.w, l4.w);
    hi[i] = h4;
    lo[i] = l4;
}

// ---------------------------------------------------------------------------
// Pre-split 3xTF32 tensor-core GEMM (R11 layout, proven 13789us).
// A and W given as (hi, lo) tf32-valued fp32 buffers. Inner loop pure LDS+MMA.
// acc += Ah*Wh + Al*Wh + Ah*Wl.
// BM=128, BN=128, BK=16, 3 stages, 256 threads, warp tile 64x32 (2m x 4n),
// mma.m16n8k8.tf32, 2 CTAs/SM.
// blockIdx.z==1 switches to the second problem {Ah2,Al2,Wh2,Wl2,bias2,Cz2}
// (merged GRU GEMMs). Epilogue: bias (+relu); raw C, dup C2, split Chi/Clo.
// ---------------------------------------------------------------------------
#define BM 128
#define BN 128
#define BK 16
#define STAGES 3
#define AS2 20                       // 16 + 4 pad
#define BS2 136                      // 128 + 8 pad
#define A_F2 (BM * AS2)              // 2560 floats per half
#define B_F2 (BK * BS2)              // 2176 floats per half
#define STG_F2 (2 * A_F2 + 2 * B_F2) // 9472 floats
#define GEMM_SMEM_BYTES (STAGES * STG_F2 * 4)  // 113,664 B

__device__ __forceinline__ void cp_async16(float* s, const float* g, bool pred)
{
    unsigned saddr = (unsigned)__cvta_generic_to_shared(s);
    int sz = pred ? 16 : 0;
    asm volatile("cp.async.cg.shared.global [%0], [%1], 16, %2;\n"
                 :: "r"(saddr), "l"(g), "r"(sz));
}

__device__ __forceinline__ void mma_tf32(float* d, const uint32_t* a, const uint32_t* b)
{
    asm volatile(
        "mma.sync.aligned.m16n8k8.row.col.f32.tf32.tf32.f32 "
        "{%0,%1,%2,%3}, {%4,%5,%6,%7}, {%8,%9}, {%0,%1,%2,%3};"
        : "+f"(d[0]), "+f"(d[1]), "+f"(d[2]), "+f"(d[3])
        : "r"(a[0]), "r"(a[1]), "r"(a[2]), "r"(a[3]), "r"(b[0]), "r"(b[1]));
}

__device__ __forceinline__ void load_stage_ps(float* sbase,
                                              const float* __restrict__ Ah,
                                              const float* __restrict__ Al,
                                              const float* __restrict__ Wh,
                                              const float* __restrict__ Wl,
                                              int M, int K, int Nc,
                                              int bm, int bn, int k0, int tid)
{
    float* sAh = sbase;
    float* sAl = sbase + A_F2;
    float* sBh = sbase + 2 * A_F2;
    float* sBl = sBh + B_F2;
    // A: 128 rows x 16 floats = 512 f4 per half; 2 f4/thread/half
    int arow = tid >> 1;               // 0..127
    int af   = (tid & 1) * 2;          // f4 idx 0 or 2
    size_t aoff = (size_t)(bm + arow) * K + k0 + af * 4;
    float* sa = sAh + arow * AS2 + af * 4;
    float* sl = sAl + arow * AS2 + af * 4;
    bool av = (bm + arow) < M;
    cp_async16(sa,     Ah + aoff,     av);
    cp_async16(sa + 4, Ah + aoff + 4, av);
    cp_async16(sl,     Al + aoff,     av);
    cp_async16(sl + 4, Al + aoff + 4, av);
    // B: 16 rows x 128 floats = 512 f4 per half; 2 f4/thread/half
    int brow = tid >> 4;               // 0..15
    int bc   = tid & 15;               // 0..15
    size_t boff = (size_t)(k0 + brow) * Nc + bn + bc * 4;
    float* sb = sBh + brow * BS2 + bc * 4;
    float* sbl = sBl + brow * BS2 + bc * 4;
    cp_async16(sb,      Wh + boff,      true);
    cp_async16(sb + 64, Wh + boff + 64, true);
    cp_async16(sbl,      Wl + boff,      true);
    cp_async16(sbl + 64, Wl + boff + 64, true);
}

__global__ __launch_bounds__(256, 2)
void tf32gemm_ps(const float* __restrict__ Ah, const float* __restrict__ Al,
                 const float* __restrict__ Wh, const float* __restrict__ Wl,
                 const float* __restrict__ bias,
                 float* __restrict__ C,
                 const float* __restrict__ Ah2, const float* __restrict__ Al2,
                 const float* __restrict__ Wh2, const float* __restrict__ Wl2,
                 const float* __restrict__ bias2, float* __restrict__ Cz2,
                 float* __restrict__ C2,
                 float* __restrict__ Chi, float* __restrict__ Clo,
                 int M, int K, int Nc, int do_relu)
{
    if (blockIdx.z == 1) { Ah = Ah2; Al = Al2; Wh = Wh2; Wl = Wl2; bias = bias2; C = Cz2; }

    extern __shared__ float smem[];
    const int tid  = threadIdx.x;
    const int bm   = blockIdx.y * BM;
    const int bn   = blockIdx.x * BN;
    const int warp = tid >> 5, lane = tid & 31;
    const int wm   = (warp >> 2) * 64;   // 0 or 64
    const int wn   = (warp & 3) * 32;    // 0,32,64,96
    const int gid  = lane >> 2, tig = lane & 3;

    float acc[4][4][4];
#pragma unroll
    for (int mt = 0; mt < 4; mt++)
#pragma unroll
        for (int nt = 0; nt < 4; nt++)
#pragma unroll
            for (int r = 0; r < 4; r++) acc[mt][nt][r] = 0.f;

    const int kTiles = K / BK;

    load_stage_ps(smem, Ah, Al, Wh, Wl, M, K, Nc, bm, bn, 0, tid);
    asm volatile("cp.async.commit_group;\n");
    load_stage_ps(smem + STG_F2, Ah, Al, Wh, Wl, M, K, Nc, bm, bn, BK, tid);
    asm volatile("cp.async.commit_group;\n");
    asm volatile("cp.async.wait_group 1;\n");
    __syncthreads();

    for (int kt = 0; kt < kTiles; kt++) {
        float* sAh = smem + (kt % STAGES) * STG_F2;
        float* sAl = sAh + A_F2;
        float* sBh = sAh + 2 * A_F2;
        float* sBl = sBh + B_F2;

        if (kt + 2 < kTiles)
            load_stage_ps(smem + ((kt + 2) % STAGES) * STG_F2,
                          Ah, Al, Wh, Wl, M, K, Nc, bm, bn, (kt + 2) * BK, tid);
        asm volatile("cp.async.commit_group;\n");

#pragma unroll
        for (int ks = 0; ks < 2; ks++) {
            const int c0 = ks * 8 + tig, c1 = c0 + 4;
            uint32_t ah[4][4], al[4][4];
#pragma unroll
            for (int mt = 0; mt < 4; mt++) {
                int r0 = wm + mt * 16 + gid;
                ah[mt][0] = __float_as_uint(sAh[r0 * AS2 + c0]);
                ah[mt][1] = __float_as_uint(sAh[(r0 + 8) * AS2 + c0]);
                ah[mt][2] = __float_as_uint(sAh[r0 * AS2 + c1]);
                ah[mt][3] = __float_as_uint(sAh[(r0 + 8) * AS2 + c1]);
                al[mt][0] = __float_as_uint(sAl[r0 * AS2 + c0]);
                al[mt][1] = __float_as_uint(sAl[(r0 + 8) * AS2 + c0]);
                al[mt][2] = __float_as_uint(sAl[r0 * AS2 + c1]);
                al[mt][3] = __float_as_uint(sAl[(r0 + 8) * AS2 + c1]);
            }
#pragma unroll
            for (int nt = 0; nt < 4; nt++) {
                int col = wn + nt * 8 + gid;
                uint32_t bh[2], bl[2];
                bh[0] = __float_as_uint(sBh[c0 * BS2 + col]);
                bh[1] = __float_as_uint(sBh[c1 * BS2 + col]);
                bl[0] = __float_as_uint(sBl[c0 * BS2 + col]);
                bl[1] = __float_as_uint(sBl[c1 * BS2 + col]);
#pragma unroll
                for (int mt = 0; mt < 4; mt++) {
                    mma_tf32(acc[mt][nt], ah[mt], bh);   // hi*hi
                    mma_tf32(acc[mt][nt], al[mt], bh);   // lo*hi
                    mma_tf32(acc[mt][nt], ah[mt], bl);   // hi*lo
                }
            }
        }

        asm volatile("cp.async.wait_group 1;\n");
        __syncthreads();
    }

    // Epilogue: bias (+relu); optional raw, dup, and split stores
#pragma unroll
    for (int nt = 0; nt < 4; nt++) {
        int col = bn + wn + nt * 8 + tig * 2;
        float b0 = bias[col], b1 = bias[col + 1];
#pragma unroll
        for (int mt = 0; mt < 4; mt++) {
            int r0 = bm + wm + mt * 16 + gid;
            int r1 = r0 + 8;
            float v0 = acc[mt][nt][0] + b0;
            float v1 = acc[mt][nt][1] + b1;
            float v2 = acc[mt][nt][2] + b0;
            float v3 = acc[mt][nt][3] + b1;
            if (do_relu) {
                v0 = fmaxf(v0, 0.f); v1 = fmaxf(v1, 0.f);
                v2 = fmaxf(v2, 0.f); v3 = fmaxf(v3, 0.f);
            }
            if (r0 < M) {
                size_t o = (size_t)r0 * Nc + col;
                if (C)  *(float2*)(C + o)  = make_float2(v0, v1);
                if (C2) *(float2*)(C2 + o) = make_float2(v0, v1);
                if (Chi) {
                    float h0, l0, h1, l1;
                    split_tf32(v0, h0, l0); split_tf32(v1, h1, l1);
                    *(float2*)(Chi + o) = make_float2(h0, h1);
                    *(float2*)(Clo + o) = make_float2(l0, l1);
                }
            }
            if (r1 < M) {
                size_t o = (size_t)r1 * Nc + col;
                if (C)  *(float2*)(C + o)  = make_float2(v2, v3);
                if (C2) *(float2*)(C2 + o) = make_float2(v2, v3);
                if (Chi) {
                    float h2, l2, h3, l3;
                    split_tf32(v2, h2, l2); split_tf32(v3, h3, l3);
                    *(float2*)(Chi + o) = make_float2(h2, h3);
                    *(float2*)(Clo + o) = make_float2(l2, l3);
                }
            }
        }
    }
}

// ---------------------------------------------------------------------------
// SIMT SGEMM (encoder only, K=24): h = x@W + bias, also emits h hi/lo splits
// ---------------------------------------------------------------------------
__global__ __launch_bounds__(256, 2)
void sgemm_enc(const float* __restrict__ A, const float* __restrict__ W,
               const float* __restrict__ bias, float* __restrict__ C,
               float* __restrict__ Chi, float* __restrict__ Clo,
               int M, int K, int Nc)
{
    __shared__ float As[2][8][128];
    __shared__ float Bs[2][8][128];

    const int tid = threadIdx.x;
    const int bm = blockIdx.y * 128;
    const int bn = blockIdx.x * 128;

    const int arow = tid >> 1;
    const int acol = (tid & 1) << 2;
    const int brow = tid >> 5;
    const int bcol = (tid & 31) << 2;
    const int ty = tid >> 4;
    const int tx = tid & 15;

    float acc[8][8];
#pragma unroll
    for (int i = 0; i < 8; i++)
#pragma unroll
        for (int j = 0; j < 8; j++) acc[i][j] = 0.f;

    const int grow = bm + arow;
    const float* Arow = A + (size_t)grow * K;

    float4 av, bv;
    av = (grow < M) ? *(const float4*)(Arow + acol) : make_float4(0.f, 0.f, 0.f, 0.f);
    bv = *(const float4*)(W + (size_t)brow * Nc + bn + bcol);
    As[0][acol + 0][arow] = av.x; As[0][acol + 1][arow] = av.y;
    As[0][acol + 2][arow] = av.z; As[0][acol + 3][arow] = av.w;
    *(float4*)&Bs[0][brow][bcol] = bv;
    __syncthreads();

    int buf = 0;
    for (int k0 = 0; k0 < K; k0 += 8) {
        const bool next = (k0 + 8) < K;
        if (next) {
            av = (grow < M) ? *(const float4*)(Arow + k0 + 8 + acol)
                            : make_float4(0.f, 0.f, 0.f, 0.f);
            bv = *(const float4*)(W + (size_t)(k0 + 8 + brow) * Nc + bn + bcol);
        }
#pragma unroll
        for (int kk = 0; kk < 8; kk++) {
            float4 a0 = *(const float4*)&As[buf][kk][ty * 8];
            float4 a1 = *(const float4*)&As[buf][kk][ty * 8 + 4];
            float4 b0 = *(const float4*)&Bs[buf][kk][tx * 8];
            float4 b1 = *(const float4*)&Bs[buf][kk][tx * 8 + 4];
            float a[8] = {a0.x, a0.y, a0.z, a0.w, a1.x, a1.y, a1.z, a1.w};
            float b[8] = {b0.x, b0.y, b0.z, b0.w, b1.x, b1.y, b1.z, b1.w};
#pragma unroll
            for (int i = 0; i < 8; i++)
#pragma unroll
                for (int j = 0; j < 8; j++)
                    acc[i][j] = fmaf(a[i], b[j], acc[i][j]);
        }
        if (next) {
            const int nbuf = buf ^ 1;
            As[nbuf][acol + 0][arow] = av.x; As[nbuf][acol + 1][arow] = av.y;
            As[nbuf][acol + 2][arow] = av.z; As[nbuf][acol + 3][arow] = av.w;
            *(float4*)&Bs[nbuf][brow][bcol] = bv;
            __syncthreads();
            buf = nbuf;
        }
    }

    float bvals[8];
#pragma unroll
    for (int j = 0; j < 8; j++) bvals[j] = bias[bn + tx * 8 + j];
#pragma unroll
    for (int i = 0; i < 8; i++) {
        int row = bm + ty * 8 + i;
        if (row >= M) continue;
        float o[8], oh[8], ol[8];
#pragma unroll
        for (int j = 0; j < 8; j++) {
            o[j] = acc[i][j] + bvals[j];
            split_tf32(o[j], oh[j], ol[j]);
        }
        size_t off = (size_t)row * Nc + bn + tx * 8;
        float4* cp = (float4*)(C + off);
        cp[0] = make_float4(o[0], o[1], o[2], o[3]);
        cp[1] = make_float4(o[4], o[5], o[6], o[7]);
        float4* ch = (float4*)(Chi + off);
        ch[0] = make_float4(oh[0], oh[1], oh[2], oh[3]);
        ch[1] = make_float4(oh[4], oh[5], oh[6], oh[7]);
        float4* cl = (float4*)(Clo + off);
        cl[0] = make_float4(ol[0], ol[1], ol[2], ol[3]);
        cl[1] = make_float4(ol[4], ol[5], ol[6], ol[7]);
    }
}

// ---------------------------------------------------------------------------
// Edge scatter: m[dst] += msg[src]  (warp/edge, vector red.global.v4.f32)
// ---------------------------------------------------------------------------
__global__ void scatter_k(const float* __restrict__ msg, float* __restrict__ m)
{
    int gw = (blockIdx.x * blockDim.x + threadIdx.x) >> 5;
    int lane = threadIdx.x & 31;
    if (gw >= EE) return;
    int s = g_eidx[gw];
    int d = g_eidx[EE + gw];
    const float4* ms = (const float4*)(msg + (size_t)s * HH);
    float4* md = (float4*)(m + (size_t)d * HH);
#pragma unroll
    for (int i = 0; i < 4; i++) {
        int c = lane + i * 32;
        float4 v = __ldg(ms + c);
        asm volatile("red.global.add.v4.f32 [%0], {%1,%2,%3,%4};"
                     :: "l"(md + c), "f"(v.x), "f"(v.y), "f"(v.z), "f"(v.w)
                     : "memory");
    }
}

// ---------------------------------------------------------------------------
// GRU gate update (in place on h), also emits h hi/lo splits
// ---------------------------------------------------------------------------
__device__ __forceinline__ float sigm_f(float x) { return 1.f / (1.f + __expf(-x)); }
__device__ __forceinline__ float tanh_f(float x) { return 1.f - 2.f / (__expf(2.f * x) + 1.f); }
__device__ __forceinline__ float gru1(float gir, float giz, float gin,
                                      float ghr, float ghz, float ghn, float h)
{
    float r = sigm_f(gir + ghr);
    float z = sigm_f(giz + ghz);
    float n = tanh_f(gin + r * ghn);
    return (1.f - z) * n + z * h;
}

__global__ void gate_k(const float* __restrict__ gi, const float* __restrict__ gh,
                       float* __restrict__ h, float* __restrict__ hhi,
                       float* __restrict__ hlo)
{
    int idx = blockIdx.x * blockDim.x + threadIdx.x;
    if (idx >= NN * (HH / 4)) return;
    int row = idx >> 7;
    int c4  = idx & 127;
    const float4* gip = (const float4*)(gi + (size_t)row * 3 * HH) + c4;
    const float4* ghp = (const float4*)(gh + (size_t)row * 3 * HH) + c4;
    float4 gir = gip[0],   giz = gip[128], gin = gip[256];
    float4 ghr = ghp[0],   ghz = ghp[128], ghn = ghp[256];
    float4 hv = ((const float4*)h)[idx];
    float4 o;
    o.x = gru1(gir.x, giz.x, gin.x, ghr.x, ghz.x, ghn.x, hv.x);
    o.y = gru1(gir.y, giz.y, gin.y, ghr.y, ghz.y, ghn.y, hv.y);
    o.z = gru1(gir.z, giz.z, gin.z, ghr.z, ghz.z, ghn.z, hv.z);
    o.w = gru1(gir.w, giz.w, gin.w, ghr.w, ghz.w, ghn.w, hv.w);
    ((float4*)h)[idx] = o;
    float4 h4, l4;
    split_tf32(o.x, h4.x, l4.x);
    split_tf32(o.y, h4.y, l4.y);
    split_tf32(o.z, h4.z, l4.z);
    split_tf32(o.w, h4.w, l4.w);
    ((float4*)hhi)[idx] = h4;
    ((float4*)hlo)[idx] = l4;
}

// ---------------------------------------------------------------------------
// Pooling + head
// ---------------------------------------------------------------------------
__global__ void zero_pool_k()
{
    int i = blockIdx.x * blockDim.x + threadIdx.x;
    if (i < GG * HH) g_pool[i] = 0.f;
    if (i < GG) g_cnt[i] = 0.f;
}

__global__ void pool_k(const float* __restrict__ h)
{
    int idx = blockIdx.x * blockDim.x + threadIdx.x;
    if (idx >= NN * 128) return;
    int row = idx >> 7;
    int c4  = idx & 127;
    int g   = g_batch[row];
    float4 v = ((const float4*)h)[idx];
    float* p = &g_pool[g * HH + c4 * 4];
    asm volatile("red.global.add.v4.f32 [%0], {%1,%2,%3,%4};"
                 :: "l"(p), "f"(v.x), "f"(v.y), "f"(v.z), "f"(v.w)
                 : "memory");
    if (c4 == 0) atomicAdd(&g_cnt[g], 1.f);
}

__global__ void head_k(const float* __restrict__ w1, const float* __restrict__ b1,
                       const float* __restrict__ w2, const float* __restrict__ b2,
                       float* __restrict__ out)
{
    __shared__ float p[HH];
    __shared__ float red[256];
    int g = blockIdx.x, t = threadIdx.x;
    float inv = 1.f / fmaxf(g_cnt[g], 1.f);
    for (int c = t; c < HH; c += 256) p[c] = g_pool[g * HH + c] * inv;
    __syncthreads();
    float acc = b1[t];
    for (int k = 0; k < HH; k++) acc = fmaf(p[k], w1[k * 256 + t], acc);
    acc = fmaxf(acc, 0.f) * w2[t];
    red[t] = acc;
    __syncthreads();
    for (int s = 128; s > 0; s >>= 1) {
        if (t < s) red[t] += red[t + s];
        __syncthreads();
    }
    if (t == 0) out[g] = red[0] + b2[0];
}

// ---------------------------------------------------------------------------
// Launch
// ---------------------------------------------------------------------------
extern "C" void kernel_launch(void* const* d_in, const int* in_sizes, int n_in,
                              void* d_out, int out_size)
{
    const float* x       = (const float*)d_in[0];
    const void*  eidx    = d_in[1];
    const void*  batch   = d_in[2];
    const float* enc_w   = (const float*)d_in[3];
    const float* enc_b   = (const float*)d_in[4];
    const float* mlp_w1  = (const float*)d_in[5];
    const float* mlp_b1  = (const float*)d_in[6];
    const float* mlp_w2  = (const float*)d_in[7];
    const float* mlp_b2  = (const float*)d_in[8];
    const float* gru_wih = (const float*)d_in[9];
    const float* gru_whh = (const float*)d_in[10];
    const float* gru_bih = (const float*)d_in[11];
    const float* gru_bhh = (const float*)d_in[12];
    const float* head_w1 = (const float*)d_in[13];
    const float* head_b1 = (const float*)d_in[14];
    const float* head_w2 = (const float*)d_in[15];
    const float* head_b2 = (const float*)d_in[16];
    float* out = (float*)d_out;

    float *ph, *phh, *phl, *pt1h, *pt1l, *pmsg, *pm, *pmh, *pml, *pgi, *pgh;
    float *pw1h, *pw1l, *pw2h, *pw2l, *pwihh, *pwihl, *pwhhh, *pwhhl;
    cudaGetSymbolAddress((void**)&ph,    g_h);
    cudaGetSymbolAddress((void**)&phh,   g_hh);
    cudaGetSymbolAddress((void**)&phl,   g_hl);
    cudaGetSymbolAddress((void**)&pt1h,  g_t1h);
    cudaGetSymbolAddress((void**)&pt1l,  g_t1l);
    cudaGetSymbolAddress((void**)&pmsg,  g_msg);
    cudaGetSymbolAddress((void**)&pm,    g_m);
    cudaGetSymbolAddress((void**)&pmh,   g_mh);
    cudaGetSymbolAddress((void**)&pml,   g_ml);
    cudaGetSymbolAddress((void**)&pgi,   g_gi);
    cudaGetSymbolAddress((void**)&pgh,   g_gh);
    cudaGetSymbolAddress((void**)&pw1h,  g_w1h);
    cudaGetSymbolAddress((void**)&pw1l,  g_w1l);
    cudaGetSymbolAddress((void**)&pw2h,  g_w2h);
    cudaGetSymbolAddress((void**)&pw2l,  g_w2l);
    cudaGetSymbolAddress((void**)&pwihh, g_wihh);
    cudaGetSymbolAddress((void**)&pwihl, g_wihl);
    cudaGetSymbolAddress((void**)&pwhhh, g_whhh);
    cudaGetSymbolAddress((void**)&pwhhl, g_whhl);

    cudaFuncSetAttribute(tf32gemm_ps, cudaFuncAttributeMaxDynamicSharedMemorySize,
                         GEMM_SMEM_BYTES);

    // dtype detection + index conversion
    detect_both_k<<<2, 256>>>((const unsigned*)eidx, (const unsigned*)batch);
    convert_both_k<<<(2 * EE + NN + 255) / 256, 256>>>(eidx, batch);

    // weight splits (once per launch)
    const int nW1 = LL * HH * HH / 4;
    const int nWG = LL * HH * 3 * HH / 4;
    split_k<<<(nW1 + 255) / 256, 256>>>((const float4*)mlp_w1,  (float4*)pw1h,  (float4*)pw1l,  nW1);
    split_k<<<(nW1 + 255) / 256, 256>>>((const float4*)mlp_w2,  (float4*)pw2h,  (float4*)pw2l,  nW1);
    split_k<<<(nWG + 255) / 256, 256>>>((const float4*)gru_wih, (float4*)pwihh, (float4*)pwihl, nWG);
    split_k<<<(nWG + 255) / 256, 256>>>((const float4*)gru_whh, (float4*)pwhhh, (float4*)pwhhl, nWG);

    dim3 gEnc(HH / 128, (NN + 127) / 128);
    dim3 gMsg(HH / BN, (NN + BM - 1) / BM, 1);           // (4, 235, 1)
    dim3 gGru(3 * HH / BN, (NN + BM - 1) / BM, 2);       // (12, 235, 2) merged
    const int nAct4 = NN * HH / 4;

    // encoder: h = x @ enc_w + enc_b (K=24, SIMT, exact fp32) + h splits
    sgemm_enc<<<gEnc, 256>>>(x, enc_w, enc_b, ph, phh, phl, NN, INC, HH);

    for (int l = 0; l < LL; l++) {
        // t1 = relu(h @ w1 + b1) -> stored pre-split only
        tf32gemm_ps<<<gMsg, 256, GEMM_SMEM_BYTES>>>(
            phh, phl, pw1h + (size_t)l * HH * HH, pw1l + (size_t)l * HH * HH,
            mlp_b1 + (size_t)l * HH, nullptr,
            nullptr, nullptr, nullptr, nullptr, nullptr, nullptr,
            nullptr, pt1h, pt1l, NN, HH, HH, 1);
        // msg = t1 @ w2 + b2 ; m = msg (self-loop) via dual store
        tf32gemm_ps<<<gMsg, 256, GEMM_SMEM_BYTES>>>(
            pt1h, pt1l, pw2h + (size_t)l * HH * HH, pw2l + (size_t)l * HH * HH,
            mlp_b2 + (size_t)l * HH, pmsg,
            nullptr, nullptr, nullptr, nullptr, nullptr, nullptr,
            pm, nullptr, nullptr, NN, HH, HH, 0);
        // m[dst] += msg[src]
        scatter_k<<<(EE + 7) / 8, 256>>>(pmsg, pm);
        // split m
        split_k<<<(nAct4 + 255) / 256, 256>>>((const float4*)pm, (float4*)pmh,
                                              (float4*)pml, nAct4);
        // merged GRU GEMMs: z=0: gi = m@wih + bih ; z=1: gh = h@whh + bhh
        tf32gemm_ps<<<gGru, 256, GEMM_SMEM_BYTES>>>(
            pmh, pml, pwihh + (size_t)l * HH * 3 * HH, pwihl + (size_t)l * HH * 3 * HH,
            gru_bih + (size_t)l * 3 * HH, pgi,
            phh, phl, pwhhh + (size_t)l * HH * 3 * HH, pwhhl + (size_t)l * HH * 3 * HH,
            gru_bhh + (size_t)l * 3 * HH, pgh,
            nullptr, nullptr, nullptr, NN, HH, 3 * HH, 0);
        // h = GRU(h, m) + h splits
        gate_k<<<(NN * 128 + 255) / 256, 256>>>(pgi, pgh, ph, phh, phl);
    }

    // global mean pool + head
    zero_pool_k<<<(GG * HH + 255) / 256, 256>>>();
    pool_k<<<(NN * 128 + 255) / 256, 256>>>(ph);
    head_k<<<GG, 256>>>(head_w1, head_b1, head_w2, head_b2, out);
}